// round 12
// baseline (speedup 1.0000x reference)
#include <cuda_runtime.h>
#include <cuda_fp16.h>
#include <math.h>
#include <stdint.h>

// Problem constants
#define M_ROWS   16384      // B*S
#define E_DIM    768
#define NQ       8
#define FFN_DIM  3072
#define LN_EPS   1e-5f

// ---------------------------------------------------------------------------
// Scratch (device globals: no cudaMalloc allowed)
// ---------------------------------------------------------------------------
__device__ __half  g_cx  [M_ROWS * E_DIM];    // cos(x + rx), fp16
__device__ float   g_z   [M_ROWS * E_DIM];    // pre-LN1
__device__ float   g_x1  [M_ROWS * E_DIM];    // LN1 output
__device__ float   g_q   [M_ROWS * NQ];
__device__ __half  g_h   [M_ROWS * FFN_DIM];  // relu(q@W1+b1), fp16
__device__ int8_t  g_h8  [M_ROWS * FFN_DIM];  // quantized h
__device__ float   g_sh  [M_ROWS];            // per-row h scale
__device__ float   g_f   [M_ROWS * E_DIM];    // pre-LN2
__device__ __half  g_WcT [E_DIM * E_DIM];     // Wc^T, fp16
__device__ int8_t  g_W2T8[E_DIM * FFN_DIM];   // W2^T, int8
__device__ unsigned g_w2max_bits;             // absmax(W2) as uint bits

// ---------------------------------------------------------------------------
// Helpers (baseline PTX only — compute_103 has no 'a' features)
// ---------------------------------------------------------------------------
__device__ __forceinline__ uint32_t smem_u32(const void* p) {
    uint32_t a;
    asm("{ .reg .u64 t; cvta.to.shared.u64 t, %1; cvt.u32.u64 %0, t; }"
        : "=r"(a) : "l"(p));
    return a;
}

__device__ __forceinline__ void cp16(uint32_t s, const void* g) {
    asm volatile("cp.async.ca.shared.global [%0], [%1], 16;" :: "r"(s), "l"(g));
}
#define CP_COMMIT() asm volatile("cp.async.commit_group;" ::: "memory")
#define CP_WAIT(n)  asm volatile("cp.async.wait_group %0;" :: "n"(n) : "memory")

__device__ __forceinline__ void ldsm4(uint32_t* r, uint32_t addr) {
    asm volatile("ldmatrix.sync.aligned.m8n8.x4.shared.b16 {%0,%1,%2,%3}, [%4];"
        : "=r"(r[0]), "=r"(r[1]), "=r"(r[2]), "=r"(r[3]) : "r"(addr));
}

__device__ __forceinline__ void mma16816(float* c, const uint32_t* a,
                                         uint32_t b0, uint32_t b1) {
    asm volatile(
        "mma.sync.aligned.m16n8k16.row.col.f32.f16.f16.f32 "
        "{%0,%1,%2,%3}, {%4,%5,%6,%7}, {%8,%9}, {%0,%1,%2,%3};"
        : "+f"(c[0]), "+f"(c[1]), "+f"(c[2]), "+f"(c[3])
        : "r"(a[0]), "r"(a[1]), "r"(a[2]), "r"(a[3]), "r"(b0), "r"(b1));
}

__device__ __forceinline__ void mma16832_s8(int* c, const uint32_t* a,
                                            uint32_t b0, uint32_t b1) {
    asm volatile(
        "mma.sync.aligned.m16n8k32.row.col.s32.s8.s8.s32 "
        "{%0,%1,%2,%3}, {%4,%5,%6,%7}, {%8,%9}, {%0,%1,%2,%3};"
        : "+r"(c[0]), "+r"(c[1]), "+r"(c[2]), "+r"(c[3])
        : "r"(a[0]), "r"(a[1]), "r"(a[2]), "r"(a[3]), "r"(b0), "r"(b1));
}

// Shared GEMM geometry (tile 256x128, rows padded to 144B stride)
#define ROW_B     144
#define A_BYTES   (256 * ROW_B)             // 36864
#define B_BYTES   (128 * ROW_B)             // 18432
#define STAGE_BYTES (A_BYTES + B_BYTES)     // 55296
#define NSTAGE    3
#define SMEM_BYTES  (NSTAGE * STAGE_BYTES)  // 165888
#define KT_F16    64                        // fp16: 64 halves = 128B payload
#define KT_I8     128                       // int8: 128 bytes = K=128

// ---------------------------------------------------------------------------
// fp16 GEMM (fp32 accumulate) — attn GEMM (K=768). Round-9 proven config.
// ---------------------------------------------------------------------------
__global__ void __launch_bounds__(256, 1)
gemm_mma_kernel(const __half* __restrict__ A, const __half* __restrict__ Bt,
                const float* __restrict__ bias, const float* __restrict__ res,
                float* __restrict__ C, int K, int NK)
{
    extern __shared__ char smem[];
    const uint32_t sbase = smem_u32(smem);

    const int tid  = threadIdx.x;
    const int w    = tid >> 5, lane = tid & 31;
    const int g    = lane >> 2, tg = lane & 3;
    const int row0 = blockIdx.y * 256;
    const int col0 = blockIdx.x * 128;
    const int wm   = (w >> 1) * 64;
    const int wn   = (w & 1) * 64;

    const int lrow = lane & 15;
    const int lsel = lane >> 4;

    const int crow = tid >> 3;
    const int cchk = tid & 7;
    const __half* Ag = A  + (size_t)(row0 + crow) * K + cchk * 8;
    const __half* Bg = Bt + (size_t)(col0 + crow) * K + cchk * 8;

    float acc[4][8][4];
    #pragma unroll
    for (int i = 0; i < 4; i++)
        #pragma unroll
        for (int j = 0; j < 8; j++)
            #pragma unroll
            for (int v = 0; v < 4; v++) acc[i][j][v] = 0.f;

    const uint32_t so = (uint32_t)crow * ROW_B + (uint32_t)cchk * 16u;

    auto issue = [&](int kt) {
        const int s = kt % NSTAGE;
        const int k0 = kt * KT_F16;
        const uint32_t sA = sbase + (uint32_t)s * STAGE_BYTES;
        const uint32_t sB = sA + A_BYTES;
        #pragma unroll
        for (int p = 0; p < 8; p++)
            cp16(sA + so + (uint32_t)(32 * p) * ROW_B,
                 Ag + (size_t)(32 * p) * K + k0);
        #pragma unroll
        for (int p = 0; p < 4; p++)
            cp16(sB + so + (uint32_t)(32 * p) * ROW_B,
                 Bg + (size_t)(32 * p) * K + k0);
        CP_COMMIT();
    };

    issue(0); issue(1);

    uint32_t af[2][4][4];
    uint32_t bf[2][4][4];

    for (int kt = 0; kt < NK; kt++) {
        const int s = kt % NSTAGE;
        CP_WAIT(1);
        __syncthreads();
        if (kt + 2 < NK) issue(kt + 2); else CP_COMMIT();

        const uint32_t sA = sbase + (uint32_t)s * STAGE_BYTES;
        const uint32_t sB = sA + A_BYTES;
        const uint32_t aB = sA + (uint32_t)(wm + lrow) * ROW_B + (uint32_t)lsel * 16u;
        const uint32_t bB = sB + (uint32_t)(wn + lrow) * ROW_B + (uint32_t)lsel * 16u;

        #pragma unroll
        for (int i = 0; i < 4; i++)
            ldsm4(af[0][i], aB + (uint32_t)(16 * i) * ROW_B);
        #pragma unroll
        for (int jj = 0; jj < 4; jj++)
            ldsm4(bf[0][jj], bB + (uint32_t)(16 * jj) * ROW_B);

        #pragma unroll
        for (int t2 = 0; t2 < 4; t2++) {
            const int cur = t2 & 1, nxt = cur ^ 1;
            if (t2 < 3) {
                const uint32_t ko = (uint32_t)(t2 + 1) * 32u;
                #pragma unroll
                for (int i = 0; i < 4; i++)
                    ldsm4(af[nxt][i], aB + (uint32_t)(16 * i) * ROW_B + ko);
                #pragma unroll
                for (int jj = 0; jj < 4; jj++)
                    ldsm4(bf[nxt][jj], bB + (uint32_t)(16 * jj) * ROW_B + ko);
            }
            #pragma unroll
            for (int i = 0; i < 4; i++)
                #pragma unroll
                for (int j = 0; j < 8; j++) {
                    const int jj = j >> 1, odd = j & 1;
                    mma16816(acc[i][j], af[cur][i],
                             bf[cur][jj][odd], bf[cur][jj][2 + odd]);
                }
        }
    }

    float2 bj[8];
    #pragma unroll
    for (int j = 0; j < 8; j++)
        bj[j] = *(const float2*)(bias + col0 + wn + 8 * j + 2 * tg);

    #pragma unroll
    for (int i = 0; i < 4; i++) {
        const int r0 = row0 + wm + 16 * i + g;
        const int r1 = r0 + 8;
        #pragma unroll
        for (int j = 0; j < 8; j++) {
            const int c = col0 + wn + 8 * j + 2 * tg;
            const size_t i0 = (size_t)r0 * E_DIM + c;
            const size_t i1 = (size_t)r1 * E_DIM + c;
            float2 rv0 = *(const float2*)(res + i0);
            float2 rv1 = *(const float2*)(res + i1);
            float2 o0, o1;
            o0.x = acc[i][j][0] + bj[j].x + rv0.x;
            o0.y = acc[i][j][1] + bj[j].y + rv0.y;
            o1.x = acc[i][j][2] + bj[j].x + rv1.x;
            o1.y = acc[i][j][3] + bj[j].y + rv1.y;
            *(float2*)(C + i0) = o0;
            *(float2*)(C + i1) = o1;
        }
    }
}

// ---------------------------------------------------------------------------
// int8 GEMM (s32 accumulate) — FFN GEMM (K=3072). Same byte geometry as fp16:
// ldmatrix.b16 fragments are byte-identical to s8 m16n8k32 fragments.
// C = (A8 @ W2T8^T) * s_h[row] * s_w2 + bias + res
// ---------------------------------------------------------------------------
__global__ void __launch_bounds__(256, 1)
gemm_mma_i8_kernel(const int8_t* __restrict__ A, const int8_t* __restrict__ Bt,
                   const float* __restrict__ sh, const unsigned* __restrict__ w2bits,
                   const float* __restrict__ bias, const float* __restrict__ res,
                   float* __restrict__ C, int K, int NK)
{
    extern __shared__ char smem[];
    const uint32_t sbase = smem_u32(smem);

    const int tid  = threadIdx.x;
    const int w    = tid >> 5, lane = tid & 31;
    const int g    = lane >> 2, tg = lane & 3;
    const int row0 = blockIdx.y * 256;
    const int col0 = blockIdx.x * 128;
    const int wm   = (w >> 1) * 64;
    const int wn   = (w & 1) * 64;

    const int lrow = lane & 15;
    const int lsel = lane >> 4;

    const int crow = tid >> 3;
    const int cchk = tid & 7;
    const int8_t* Ag = A  + (size_t)(row0 + crow) * K + cchk * 16;
    const int8_t* Bg = Bt + (size_t)(col0 + crow) * K + cchk * 16;

    int acc[4][8][4];
    #pragma unroll
    for (int i = 0; i < 4; i++)
        #pragma unroll
        for (int j = 0; j < 8; j++)
            #pragma unroll
            for (int v = 0; v < 4; v++) acc[i][j][v] = 0;

    const uint32_t so = (uint32_t)crow * ROW_B + (uint32_t)cchk * 16u;

    auto issue = [&](int kt) {
        const int s = kt % NSTAGE;
        const int k0 = kt * KT_I8;
        const uint32_t sA = sbase + (uint32_t)s * STAGE_BYTES;
        const uint32_t sB = sA + A_BYTES;
        #pragma unroll
        for (int p = 0; p < 8; p++)
            cp16(sA + so + (uint32_t)(32 * p) * ROW_B,
                 Ag + (size_t)(32 * p) * K + k0);
        #pragma unroll
        for (int p = 0; p < 4; p++)
            cp16(sB + so + (uint32_t)(32 * p) * ROW_B,
                 Bg + (size_t)(32 * p) * K + k0);
        CP_COMMIT();
    };

    issue(0); issue(1);

    uint32_t af[4][4];
    uint32_t bf[4][4];

    for (int kt = 0; kt < NK; kt++) {
        const int s = kt % NSTAGE;
        CP_WAIT(1);
        __syncthreads();
        if (kt + 2 < NK) issue(kt + 2); else CP_COMMIT();

        const uint32_t sA = sbase + (uint32_t)s * STAGE_BYTES;
        const uint32_t sB = sA + A_BYTES;
        const uint32_t aB = sA + (uint32_t)(wm + lrow) * ROW_B + (uint32_t)lsel * 16u;
        const uint32_t bB = sB + (uint32_t)(wn + lrow) * ROW_B + (uint32_t)lsel * 16u;

        #pragma unroll
        for (int t2 = 0; t2 < 4; t2++) {         // 4 x k32 per stage (K=128)
            const uint32_t ko = (uint32_t)t2 * 32u;
            #pragma unroll
            for (int i = 0; i < 4; i++)
                ldsm4(af[i], aB + (uint32_t)(16 * i) * ROW_B + ko);
            #pragma unroll
            for (int jj = 0; jj < 4; jj++)
                ldsm4(bf[jj], bB + (uint32_t)(16 * jj) * ROW_B + ko);

            #pragma unroll
            for (int i = 0; i < 4; i++)
                #pragma unroll
                for (int j = 0; j < 8; j++) {
                    const int jj = j >> 1, odd = j & 1;
                    mma16832_s8(acc[i][j], af[i],
                                bf[jj][odd], bf[jj][2 + odd]);
                }
        }
    }

    const float sw2 = __uint_as_float(*w2bits) * (1.f / 127.f);

    float2 bj[8];
    #pragma unroll
    for (int j = 0; j < 8; j++)
        bj[j] = *(const float2*)(bias + col0 + wn + 8 * j + 2 * tg);

    #pragma unroll
    for (int i = 0; i < 4; i++) {
        const int r0 = row0 + wm + 16 * i + g;
        const int r1 = r0 + 8;
        const float s0 = sh[r0] * sw2;
        const float s1 = sh[r1] * sw2;
        #pragma unroll
        for (int j = 0; j < 8; j++) {
            const int c = col0 + wn + 8 * j + 2 * tg;
            const size_t i0 = (size_t)r0 * E_DIM + c;
            const size_t i1 = (size_t)r1 * E_DIM + c;
            float2 rv0 = *(const float2*)(res + i0);
            float2 rv1 = *(const float2*)(res + i1);
            float2 o0, o1;
            o0.x = (float)acc[i][j][0] * s0 + bj[j].x + rv0.x;
            o0.y = (float)acc[i][j][1] * s0 + bj[j].y + rv0.y;
            o1.x = (float)acc[i][j][2] * s1 + bj[j].x + rv1.x;
            o1.y = (float)acc[i][j][3] * s1 + bj[j].y + rv1.y;
            *(float2*)(C + i0) = o0;
            *(float2*)(C + i1) = o1;
        }
    }
}

// ---------------------------------------------------------------------------
// W2 absmax (atomicMax on bits; floats non-negative so bit-order == order)
// ---------------------------------------------------------------------------
__global__ void initmax_kernel(unsigned* bits) { *bits = 0u; }

__global__ void __launch_bounds__(256)
absmax_kernel(const float* __restrict__ W2, int n, unsigned* bits)
{
    float m = 0.f;
    for (int i = blockIdx.x * 256 + threadIdx.x; i < n; i += gridDim.x * 256)
        m = fmaxf(m, fabsf(W2[i]));
    #pragma unroll
    for (int o = 16; o > 0; o >>= 1)
        m = fmaxf(m, __shfl_xor_sync(0xffffffffu, m, o));
    __shared__ float red[8];
    if ((threadIdx.x & 31) == 0) red[threadIdx.x >> 5] = m;
    __syncthreads();
    if (threadIdx.x == 0) {
        float bm = 0.f;
        #pragma unroll
        for (int i = 0; i < 8; i++) bm = fmaxf(bm, red[i]);
        atomicMax(bits, __float_as_uint(bm));
    }
}

// ---------------------------------------------------------------------------
// W2 quantize + transpose: W2 (K x N fp32) -> W2T8 (N x K int8), scale max/127
// ---------------------------------------------------------------------------
__global__ void __launch_bounds__(256)
w2quant_kernel(const float* __restrict__ in, int8_t* __restrict__ out,
               const unsigned* __restrict__ bits, int R, int C)
{
    __shared__ float t[32][33];
    const float mx = __uint_as_float(*bits);
    const float inv = (mx > 0.f) ? (127.f / mx) : 0.f;
    const int c0 = blockIdx.x * 32, r0 = blockIdx.y * 32;
    #pragma unroll
    for (int j = 0; j < 4; j++)
        t[threadIdx.y + j * 8][threadIdx.x] =
            in[(size_t)(r0 + threadIdx.y + j * 8) * C + (c0 + threadIdx.x)];
    __syncthreads();
    #pragma unroll
    for (int j = 0; j < 4; j++) {
        int v = __float2int_rn(t[threadIdx.x][threadIdx.y + j * 8] * inv);
        v = max(-127, min(127, v));
        out[(size_t)(c0 + threadIdx.y + j * 8) * R + (r0 + threadIdx.x)] = (int8_t)v;
    }
}

// ---------------------------------------------------------------------------
// Quantize h: fp16 row -> int8 row + per-row scale. One warp per row.
// ---------------------------------------------------------------------------
__global__ void __launch_bounds__(256)
quanth_kernel(const __half* __restrict__ h, int8_t* __restrict__ h8,
              float* __restrict__ sh)
{
    const int wid  = threadIdx.x >> 5;
    const int lane = threadIdx.x & 31;
    const int m    = blockIdx.x * 8 + wid;
    const __half* row = h + (size_t)m * FFN_DIM;

    uint4 d[12];
    float mx = 0.f;
    #pragma unroll
    for (int i = 0; i < 12; i++) {
        d[i] = *(const uint4*)((const char*)row + lane * 16 + i * 512);
        const __half2* p = (const __half2*)&d[i];
        #pragma unroll
        for (int k = 0; k < 4; k++) {
            float2 f = __half22float2(p[k]);
            mx = fmaxf(mx, fmaxf(f.x, f.y));   // h >= 0 (post-relu)
        }
    }
    #pragma unroll
    for (int o = 16; o > 0; o >>= 1)
        mx = fmaxf(mx, __shfl_xor_sync(0xffffffffu, mx, o));

    const float inv = (mx > 0.f) ? (127.f / mx) : 0.f;
    if (lane == 0) sh[m] = (mx > 0.f) ? (mx / 127.f) : 0.f;

    int8_t* orow = h8 + (size_t)m * FFN_DIM;
    #pragma unroll
    for (int i = 0; i < 12; i++) {
        const __half2* p = (const __half2*)&d[i];
        int8_t b[8];
        #pragma unroll
        for (int k = 0; k < 4; k++) {
            float2 f = __half22float2(p[k]);
            b[2 * k + 0] = (int8_t)min(127, __float2int_rn(f.x * inv));
            b[2 * k + 1] = (int8_t)min(127, __float2int_rn(f.y * inv));
        }
        *(uint2*)(orow + lane * 8 + i * 256) = *(const uint2*)b;
    }
}

// ---------------------------------------------------------------------------
// cos(x + rx) precompute -> fp16
// ---------------------------------------------------------------------------
__global__ void __launch_bounds__(256)
cosx_kernel(const float* __restrict__ x, const float* __restrict__ rx,
            __half* __restrict__ cx)
{
    const int i = blockIdx.x * 256 + threadIdx.x;
    float4 v0 = ((const float4*)x)[2 * i];
    float4 v1 = ((const float4*)x)[2 * i + 1];
    const int e = (i * 8) & 63;
    __half2 h[4];
    h[0] = __floats2half2_rn(cosf(v0.x + rx[e + 0]), cosf(v0.y + rx[e + 1]));
    h[1] = __floats2half2_rn(cosf(v0.z + rx[e + 2]), cosf(v0.w + rx[e + 3]));
    h[2] = __floats2half2_rn(cosf(v1.x + rx[e + 4]), cosf(v1.y + rx[e + 5]));
    h[3] = __floats2half2_rn(cosf(v1.z + rx[e + 6]), cosf(v1.w + rx[e + 7]));
    ((uint4*)cx)[i] = *(const uint4*)h;
}

// ---------------------------------------------------------------------------
// Transpose: in R x C (fp32) -> out C x R (fp16)
// ---------------------------------------------------------------------------
__global__ void __launch_bounds__(256)
transpose_kernel(const float* __restrict__ in, __half* __restrict__ out, int R, int C)
{
    __shared__ float t[32][33];
    const int c0 = blockIdx.x * 32, r0 = blockIdx.y * 32;
    #pragma unroll
    for (int j = 0; j < 4; j++)
        t[threadIdx.y + j * 8][threadIdx.x] =
            in[(size_t)(r0 + threadIdx.y + j * 8) * C + (c0 + threadIdx.x)];
    __syncthreads();
    #pragma unroll
    for (int j = 0; j < 4; j++)
        out[(size_t)(c0 + threadIdx.y + j * 8) * R + (r0 + threadIdx.x)] =
            __float2half_rn(t[threadIdx.x][threadIdx.y + j * 8]);
}

// ---------------------------------------------------------------------------
// Row LayerNorm over E=768 — one warp per row, barrier-free.
// ---------------------------------------------------------------------------
template <bool WRITE_Q>
__global__ void __launch_bounds__(256)
ln_kernel(const float* __restrict__ in, const float* __restrict__ g,
          const float* __restrict__ b, const float* __restrict__ ry,
          float* __restrict__ out, float* __restrict__ q)
{
    const int wid  = threadIdx.x >> 5;
    const int lane = threadIdx.x & 31;
    const int m    = blockIdx.x * 8 + wid;
    const float* row = in + (size_t)m * E_DIM;

    float4 v[6];
    float s = 0.f, ss = 0.f;
    #pragma unroll
    for (int i = 0; i < 6; i++) {
        v[i] = *(const float4*)(row + lane * 4 + i * 128);
        s  += v[i].x + v[i].y + v[i].z + v[i].w;
        ss += v[i].x * v[i].x + v[i].y * v[i].y
            + v[i].z * v[i].z + v[i].w * v[i].w;
    }
    #pragma unroll
    for (int o = 16; o > 0; o >>= 1) {
        s  += __shfl_xor_sync(0xffffffffu, s,  o);
        ss += __shfl_xor_sync(0xffffffffu, ss, o);
    }

    const float mu  = s * (1.f / E_DIM);
    const float var = ss * (1.f / E_DIM) - mu * mu;
    const float inv = rsqrtf(var + LN_EPS);

    float* orow = out + (size_t)m * E_DIM;
    #pragma unroll
    for (int i = 0; i < 6; i++) {
        const int c = lane * 4 + i * 128;
        const float4 gv = *(const float4*)(g + c);
        const float4 bv = *(const float4*)(b + c);
        float4 y;
        y.x = (v[i].x - mu) * inv * gv.x + bv.x;
        y.y = (v[i].y - mu) * inv * gv.y + bv.y;
        y.z = (v[i].z - mu) * inv * gv.z + bv.z;
        y.w = (v[i].w - mu) * inv * gv.w + bv.w;
        *(float4*)(orow + c) = y;
        if (WRITE_Q && i == 0 && lane < 2) {
            const int c0 = lane * 4;
            q[(size_t)m * NQ + c0 + 0] = cosf(y.x) * cosf(ry[c0 + 0]);
            q[(size_t)m * NQ + c0 + 1] = cosf(y.y) * cosf(ry[c0 + 1]);
            q[(size_t)m * NQ + c0 + 2] = cosf(y.z) * cosf(ry[c0 + 2]);
            q[(size_t)m * NQ + c0 + 3] = cosf(y.w) * cosf(ry[c0 + 3]);
        }
    }
}

// ---------------------------------------------------------------------------
// FFN first layer (tiled): h = relu(q @ W1 + b1) -> fp16.
// ---------------------------------------------------------------------------
__global__ void __launch_bounds__(256)
ffn1_kernel(const float* __restrict__ q, const float* __restrict__ W1,
            const float* __restrict__ b1, __half* __restrict__ h)
{
    __shared__ float w1s[NQ][1024];
    __shared__ float b1s[1024];
    __shared__ float qs[256][NQ];

    const int col0 = blockIdx.x * 1024;
    const int m0   = blockIdx.y * 256;
    const int tid  = threadIdx.x;

    #pragma unroll
    for (int i = 0; i < NQ; i++)
        *(float4*)&w1s[i][tid * 4] =
            *(const float4*)(W1 + (size_t)i * FFN_DIM + col0 + tid * 4);
    *(float4*)&b1s[tid * 4] = *(const float4*)(b1 + col0 + tid * 4);
    {
        const int r = tid;
        float2 q01 = *(const float2*)(q + (size_t)(m0 + r) * NQ + 0);
        float2 q23 = *(const float2*)(q + (size_t)(m0 + r) * NQ + 2);
        float2 q45 = *(const float2*)(q + (size_t)(m0 + r) * NQ + 4);
        float2 q67 = *(const float2*)(q + (size_t)(m0 + r) * NQ + 6);
        qs[r][0] = q01.x; qs[r][1] = q01.y;
        qs[r][2] = q23.x; qs[r][3] = q23.y;
        qs[r][4] = q45.x; qs[r][5] = q45.y;
        qs[r][6] = q67.x; qs[r][7] = q67.y;
    }
    __syncthreads();

    float4 wr[NQ];
    #pragma unroll
    for (int i = 0; i < NQ; i++) wr[i] = *(float4*)&w1s[i][tid * 4];
    const float4 bb = *(float4*)&b1s[tid * 4];

    __half* hp = h + (size_t)m0 * FFN_DIM + col0 + tid * 4;
    for (int r = 0; r < 256; r++) {
        float4 acc = bb;
        #pragma unroll
        for (int i = 0; i < NQ; i++) {
            const float qv = qs[r][i];
            acc.x = fmaf(qv, wr[i].x, acc.x);
            acc.y = fmaf(qv, wr[i].y, acc.y);
            acc.z = fmaf(qv, wr[i].z, acc.z);
            acc.w = fmaf(qv, wr[i].w, acc.w);
        }
        __half2 p0 = __floats2half2_rn(fmaxf(acc.x, 0.f), fmaxf(acc.y, 0.f));
        __half2 p1 = __floats2half2_rn(fmaxf(acc.z, 0.f), fmaxf(acc.w, 0.f));
        uint2 pk = make_uint2(*(uint32_t*)&p0, *(uint32_t*)&p1);
        *(uint2*)(hp + (size_t)r * FFN_DIM) = pk;
    }
}

// ---------------------------------------------------------------------------
// Launch
// ---------------------------------------------------------------------------
extern "C" void kernel_launch(void* const* d_in, const int* in_sizes, int n_in,
                              void* d_out, int out_size)
{
    const float* x   = (const float*)d_in[0];
    const float* rx  = (const float*)d_in[1];
    const float* ry  = (const float*)d_in[2];
    const float* Wc  = (const float*)d_in[3];
    const float* bc  = (const float*)d_in[4];
    const float* W1  = (const float*)d_in[5];
    const float* b1  = (const float*)d_in[6];
    const float* W2  = (const float*)d_in[7];
    const float* b2  = (const float*)d_in[8];
    const float* g1  = (const float*)d_in[9];
    const float* be1 = (const float*)d_in[10];
    const float* g2  = (const float*)d_in[11];
    const float* be2 = (const float*)d_in[12];
    float* out = (float*)d_out;

    __half *cx, *h, *WcT;
    int8_t *h8, *W2T8;
    float *z, *x1, *q, *f, *sh;
    unsigned* w2bits;
    cudaGetSymbolAddress((void**)&cx,    g_cx);
    cudaGetSymbolAddress((void**)&z,     g_z);
    cudaGetSymbolAddress((void**)&x1,    g_x1);
    cudaGetSymbolAddress((void**)&q,     g_q);
    cudaGetSymbolAddress((void**)&h,     g_h);
    cudaGetSymbolAddress((void**)&h8,    g_h8);
    cudaGetSymbolAddress((void**)&sh,    g_sh);
    cudaGetSymbolAddress((void**)&f,     g_f);
    cudaGetSymbolAddress((void**)&WcT,   g_WcT);
    cudaGetSymbolAddress((void**)&W2T8,  g_W2T8);
    cudaGetSymbolAddress((void**)&w2bits, g_w2max_bits);

    cudaFuncSetAttribute(gemm_mma_kernel,
                         cudaFuncAttributeMaxDynamicSharedMemorySize, SMEM_BYTES);
    cudaFuncSetAttribute(gemm_mma_i8_kernel,
                         cudaFuncAttributeMaxDynamicSharedMemorySize, SMEM_BYTES);

    // 0) W2 int8 prep + Wc transpose + cos precompute
    initmax_kernel<<<1, 1>>>(w2bits);
    absmax_kernel<<<512, 256>>>(W2, FFN_DIM * E_DIM, w2bits);
    w2quant_kernel<<<dim3(E_DIM / 32, FFN_DIM / 32), dim3(32, 8)>>>(
        W2, W2T8, w2bits, FFN_DIM, E_DIM);
    transpose_kernel<<<dim3(E_DIM / 32, E_DIM / 32), dim3(32, 8)>>>(Wc, WcT, E_DIM, E_DIM);
    cosx_kernel<<<(M_ROWS * E_DIM / 8) / 256, 256>>>(x, rx, cx);

    // 1) z = cos(x+rx) @ Wc + bc + x        (fp16 mma)
    gemm_mma_kernel<<<dim3(E_DIM / 128, M_ROWS / 256), 256, SMEM_BYTES>>>(
        cx, WcT, bc, x, z, E_DIM, E_DIM / KT_F16);

    // 2) x1 = LN(z); q = cos(x1[:, :8]) * cos(ry)
    ln_kernel<true><<<M_ROWS / 8, 256>>>(z, g1, be1, ry, x1, q);

    // 3) h = relu(q @ W1 + b1) -> fp16; quantize to int8 + per-row scale
    ffn1_kernel<<<dim3(FFN_DIM / 1024, M_ROWS / 256), 256>>>(q, W1, b1, h);
    quanth_kernel<<<M_ROWS / 8, 256>>>(h, h8, sh);

    // 4) f = dequant(h8 @ W2T8) + b2 + x1   (int8 mma, 2x FLOP/instr)
    gemm_mma_i8_kernel<<<dim3(E_DIM / 128, M_ROWS / 256), 256, SMEM_BYTES>>>(
        h8, W2T8, sh, w2bits, b2, x1, f, FFN_DIM, FFN_DIM / KT_I8);

    // 5) out = LN(f)
    ln_kernel<false><<<M_ROWS / 8, 256>>>(f, g2, be2, nullptr, out, nullptr);
}

// round 14
// speedup vs baseline: 1.5788x; 1.5788x over previous
#include <cuda_runtime.h>
#include <cuda_fp16.h>
#include <math.h>
#include <stdint.h>

// Problem constants
#define M_ROWS   16384      // B*S
#define E_DIM    768
#define NQ       8
#define FFN_DIM  3072
#define LN_EPS   1e-5f

// ---------------------------------------------------------------------------
// Scratch (device globals: no cudaMalloc allowed)
// ---------------------------------------------------------------------------
__device__ __half  g_cx  [M_ROWS * E_DIM];    // cos(x + rx), fp16
__device__ float   g_z   [M_ROWS * E_DIM];    // pre-LN1
__device__ float   g_x1  [M_ROWS * E_DIM];    // LN1 output
__device__ __half2 g_q16d[M_ROWS * NQ];       // q, each value DUPLICATED in half2
__device__ float   g_f   [M_ROWS * E_DIM];    // pre-LN2
__device__ __half  g_WcT [E_DIM * E_DIM];     // Wc^T, fp16
__device__ __half  g_W2T [E_DIM * FFN_DIM];   // W2^T, fp16
__device__ __half  g_W1h [NQ * FFN_DIM];      // W1, fp16
__device__ __half  g_b1h [FFN_DIM];           // b1, fp16

// ---------------------------------------------------------------------------
// Helpers (baseline PTX only — compute_103 has no 'a' features)
// ---------------------------------------------------------------------------
__device__ __forceinline__ uint32_t smem_u32(const void* p) {
    uint32_t a;
    asm("{ .reg .u64 t; cvta.to.shared.u64 t, %1; cvt.u32.u64 %0, t; }"
        : "=r"(a) : "l"(p));
    return a;
}

__device__ __forceinline__ void cp16(uint32_t s, const void* g) {
    asm volatile("cp.async.ca.shared.global [%0], [%1], 16;" :: "r"(s), "l"(g));
}
#define CP_COMMIT() asm volatile("cp.async.commit_group;" ::: "memory")
#define CP_WAIT(n)  asm volatile("cp.async.wait_group %0;" :: "n"(n) : "memory")

__device__ __forceinline__ void ldsm4(uint32_t* r, uint32_t addr) {
    asm volatile("ldmatrix.sync.aligned.m8n8.x4.shared.b16 {%0,%1,%2,%3}, [%4];"
        : "=r"(r[0]), "=r"(r[1]), "=r"(r[2]), "=r"(r[3]) : "r"(addr));
}

__device__ __forceinline__ void mma16816(float* c, const uint32_t* a,
                                         uint32_t b0, uint32_t b1) {
    asm volatile(
        "mma.sync.aligned.m16n8k16.row.col.f32.f16.f16.f32 "
        "{%0,%1,%2,%3}, {%4,%5,%6,%7}, {%8,%9}, {%0,%1,%2,%3};"
        : "+f"(c[0]), "+f"(c[1]), "+f"(c[2]), "+f"(c[3])
        : "r"(a[0]), "r"(a[1]), "r"(a[2]), "r"(a[3]), "r"(b0), "r"(b1));
}

// Shared GEMM geometry (tile 256x128, rows padded to 144B stride)
#define KT        64
#define ROW_B     144
#define A_BYTES   (256 * ROW_B)             // 36864
#define B_BYTES   (128 * ROW_B)             // 18432

// GEMM1 (cp.async A+B, 3 stages)
#define STAGE1_BYTES (A_BYTES + B_BYTES)    // 55296
#define NSTAGE    3
#define SMEM1_BYTES  (NSTAGE * STAGE1_BYTES)  // 165888

// Fused GEMM2: A single buffer (computed), B 3-stage
#define SMEM2_BYTES  (A_BYTES + NSTAGE * B_BYTES)  // 92160

// ---------------------------------------------------------------------------
// fp16 GEMM (fp32 accumulate) — attn GEMM (K=768). Round-10 proven config.
// ---------------------------------------------------------------------------
__global__ void __launch_bounds__(256, 1)
gemm_mma_kernel(const __half* __restrict__ A, const __half* __restrict__ Bt,
                const float* __restrict__ bias, const float* __restrict__ res,
                float* __restrict__ C, int K, int NK)
{
    extern __shared__ char smem[];
    const uint32_t sbase = smem_u32(smem);

    const int tid  = threadIdx.x;
    const int w    = tid >> 5, lane = tid & 31;
    const int g    = lane >> 2, tg = lane & 3;
    const int row0 = blockIdx.y * 256;
    const int col0 = blockIdx.x * 128;
    const int wm   = (w >> 1) * 64;
    const int wn   = (w & 1) * 64;

    const int lrow = lane & 15;
    const int lsel = lane >> 4;

    const int crow = tid >> 3;
    const int cchk = tid & 7;
    const __half* Ag = A  + (size_t)(row0 + crow) * K + cchk * 8;
    const __half* Bg = Bt + (size_t)(col0 + crow) * K + cchk * 8;

    float acc[4][8][4];
    #pragma unroll
    for (int i = 0; i < 4; i++)
        #pragma unroll
        for (int j = 0; j < 8; j++)
            #pragma unroll
            for (int v = 0; v < 4; v++) acc[i][j][v] = 0.f;

    const uint32_t so = (uint32_t)crow * ROW_B + (uint32_t)cchk * 16u;

    auto issue = [&](int kt) {
        const int s = kt % NSTAGE;
        const int k0 = kt * KT;
        const uint32_t sA = sbase + (uint32_t)s * STAGE1_BYTES;
        const uint32_t sB = sA + A_BYTES;
        #pragma unroll
        for (int p = 0; p < 8; p++)
            cp16(sA + so + (uint32_t)(32 * p) * ROW_B,
                 Ag + (size_t)(32 * p) * K + k0);
        #pragma unroll
        for (int p = 0; p < 4; p++)
            cp16(sB + so + (uint32_t)(32 * p) * ROW_B,
                 Bg + (size_t)(32 * p) * K + k0);
        CP_COMMIT();
    };

    issue(0); issue(1);

    uint32_t af[2][4][4];
    uint32_t bf[2][4][4];

    for (int kt = 0; kt < NK; kt++) {
        const int s = kt % NSTAGE;
        CP_WAIT(1);
        __syncthreads();
        if (kt + 2 < NK) issue(kt + 2); else CP_COMMIT();

        const uint32_t sA = sbase + (uint32_t)s * STAGE1_BYTES;
        const uint32_t sB = sA + A_BYTES;
        const uint32_t aB = sA + (uint32_t)(wm + lrow) * ROW_B + (uint32_t)lsel * 16u;
        const uint32_t bB = sB + (uint32_t)(wn + lrow) * ROW_B + (uint32_t)lsel * 16u;

        #pragma unroll
        for (int i = 0; i < 4; i++)
            ldsm4(af[0][i], aB + (uint32_t)(16 * i) * ROW_B);
        #pragma unroll
        for (int jj = 0; jj < 4; jj++)
            ldsm4(bf[0][jj], bB + (uint32_t)(16 * jj) * ROW_B);

        #pragma unroll
        for (int t2 = 0; t2 < 4; t2++) {
            const int cur = t2 & 1, nxt = cur ^ 1;
            if (t2 < 3) {
                const uint32_t ko = (uint32_t)(t2 + 1) * 32u;
                #pragma unroll
                for (int i = 0; i < 4; i++)
                    ldsm4(af[nxt][i], aB + (uint32_t)(16 * i) * ROW_B + ko);
                #pragma unroll
                for (int jj = 0; jj < 4; jj++)
                    ldsm4(bf[nxt][jj], bB + (uint32_t)(16 * jj) * ROW_B + ko);
            }
            #pragma unroll
            for (int i = 0; i < 4; i++)
                #pragma unroll
                for (int j = 0; j < 8; j++) {
                    const int jj = j >> 1, odd = j & 1;
                    mma16816(acc[i][j], af[cur][i],
                             bf[cur][jj][odd], bf[cur][jj][2 + odd]);
                }
        }
    }

    float2 bj[8];
    #pragma unroll
    for (int j = 0; j < 8; j++)
        bj[j] = *(const float2*)(bias + col0 + wn + 8 * j + 2 * tg);

    #pragma unroll
    for (int i = 0; i < 4; i++) {
        const int r0 = row0 + wm + 16 * i + g;
        const int r1 = r0 + 8;
        #pragma unroll
        for (int j = 0; j < 8; j++) {
            const int c = col0 + wn + 8 * j + 2 * tg;
            const size_t i0 = (size_t)r0 * E_DIM + c;
            const size_t i1 = (size_t)r1 * E_DIM + c;
            float2 rv0 = *(const float2*)(res + i0);
            float2 rv1 = *(const float2*)(res + i1);
            float2 o0, o1;
            o0.x = acc[i][j][0] + bj[j].x + rv0.x;
            o0.y = acc[i][j][1] + bj[j].y + rv0.y;
            o1.x = acc[i][j][2] + bj[j].x + rv1.x;
            o1.y = acc[i][j][3] + bj[j].y + rv1.y;
            *(float2*)(C + i0) = o0;
            *(float2*)(C + i1) = o1;
        }
    }
}

// ---------------------------------------------------------------------------
// FUSED FFN GEMM: f = relu(q@W1+b1) @ W2^T + b2 + x1
// A-tile (h, 256x64 fp16) is COMPUTED in-kernel (K=8 producer on the fma
// pipe, operands L1-hot) into a single smem buffer; B (W2T) via 3-stage
// cp.async. Mainloop identical to the proven fp16 MMA loop.
// ---------------------------------------------------------------------------
__global__ void __launch_bounds__(256, 1)
gemm_ffn_kernel(const __half2* __restrict__ q16d,   // [M][8] duplicated half2
                const __half* __restrict__ W1h,     // [8][3072]
                const __half* __restrict__ b1h,     // [3072]
                const __half* __restrict__ Bt,      // W2T [768][3072]
                const float* __restrict__ bias,     // b2
                const float* __restrict__ res,      // x1
                float* __restrict__ C, int K, int NK)
{
    extern __shared__ char smem[];
    const uint32_t sbase = smem_u32(smem);          // A buffer at base
    const uint32_t bbase = sbase + A_BYTES;         // 3 B stages follow

    const int tid  = threadIdx.x;
    const int w    = tid >> 5, lane = tid & 31;
    const int g    = lane >> 2, tg = lane & 3;
    const int row0 = blockIdx.y * 256;
    const int col0 = blockIdx.x * 128;
    const int wm   = (w >> 1) * 64;
    const int wn   = (w & 1) * 64;

    const int lrow = lane & 15;
    const int lsel = lane >> 4;

    const int crow = tid >> 3;                      // 0..31
    const int cchk = tid & 7;                       // col group (8 cols)
    const __half* Bg = Bt + (size_t)(col0 + crow) * K + cchk * 8;

    float acc[4][8][4];
    #pragma unroll
    for (int i = 0; i < 4; i++)
        #pragma unroll
        for (int j = 0; j < 8; j++)
            #pragma unroll
            for (int v = 0; v < 4; v++) acc[i][j][v] = 0.f;

    const uint32_t so = (uint32_t)crow * ROW_B + (uint32_t)cchk * 16u;

    auto issueB = [&](int kt) {
        const int s = kt % NSTAGE;
        const int k0 = kt * KT;
        const uint32_t sB = bbase + (uint32_t)s * B_BYTES;
        #pragma unroll
        for (int p = 0; p < 4; p++)
            cp16(sB + so + (uint32_t)(32 * p) * ROW_B,
                 Bg + (size_t)(32 * p) * K + k0);
        CP_COMMIT();
    };

    issueB(0); issueB(1);

    uint32_t af[4][4];
    uint32_t bf[4][4];
    const __half2 zero2 = __float2half2_rn(0.f);

    for (int kt = 0; kt < NK; kt++) {
        const int s = kt % NSTAGE;
        const int k0 = kt * KT;
        CP_WAIT(1);
        __syncthreads();                 // B[kt] visible; A reads of kt-1 done
        if (kt + 2 < NK) issueB(kt + 2); else CP_COMMIT();

        // ---- producer: compute h tile (256 x 64) into A smem ----
        // thread's 8 cols: k0 + cchk*8 .. +7
        uint4 w1r[NQ];                   // 8 halves per i
        #pragma unroll
        for (int i = 0; i < NQ; i++)
            w1r[i] = *(const uint4*)(W1h + (size_t)i * FFN_DIM + k0 + cchk * 8);
        const uint4 b1r = *(const uint4*)(b1h + k0 + cchk * 8);

        #pragma unroll
        for (int p = 0; p < 8; p++) {
            const int row = row0 + crow + 32 * p;
            const __half2* qd = q16d + (size_t)row * NQ;
            uint4 q03 = *(const uint4*)(qd);        // dup q0..q3
            uint4 q47 = *(const uint4*)(qd + 4);    // dup q4..q7
            const __half2* qv = (const __half2*)&q03;
            const __half2* qw = (const __half2*)&q47;

            __half2 a0 = ((const __half2*)&b1r)[0];
            __half2 a1 = ((const __half2*)&b1r)[1];
            __half2 a2 = ((const __half2*)&b1r)[2];
            __half2 a3 = ((const __half2*)&b1r)[3];
            #pragma unroll
            for (int i = 0; i < 4; i++) {
                const __half2* wv = (const __half2*)&w1r[i];
                a0 = __hfma2(qv[i], wv[0], a0);
                a1 = __hfma2(qv[i], wv[1], a1);
                a2 = __hfma2(qv[i], wv[2], a2);
                a3 = __hfma2(qv[i], wv[3], a3);
            }
            #pragma unroll
            for (int i = 0; i < 4; i++) {
                const __half2* wv = (const __half2*)&w1r[4 + i];
                a0 = __hfma2(qw[i], wv[0], a0);
                a1 = __hfma2(qw[i], wv[1], a1);
                a2 = __hfma2(qw[i], wv[2], a2);
                a3 = __hfma2(qw[i], wv[3], a3);
            }
            a0 = __hmax2(a0, zero2);
            a1 = __hmax2(a1, zero2);
            a2 = __hmax2(a2, zero2);
            a3 = __hmax2(a3, zero2);
            uint4 pk;
            pk.x = *(uint32_t*)&a0; pk.y = *(uint32_t*)&a1;
            pk.z = *(uint32_t*)&a2; pk.w = *(uint32_t*)&a3;
            *(uint4*)(smem + so + (uint32_t)(32 * p) * ROW_B) = pk;
        }
        __syncthreads();                 // A writes visible to all warps

        // ---- mainloop: ldmatrix + MMA (A single buffer, B stage s) ----
        const uint32_t sB = bbase + (uint32_t)s * B_BYTES;
        const uint32_t aB = sbase + (uint32_t)(wm + lrow) * ROW_B + (uint32_t)lsel * 16u;
        const uint32_t bB = sB + (uint32_t)(wn + lrow) * ROW_B + (uint32_t)lsel * 16u;

        #pragma unroll
        for (int t2 = 0; t2 < 4; t2++) {
            const uint32_t ko = (uint32_t)t2 * 32u;
            #pragma unroll
            for (int i = 0; i < 4; i++)
                ldsm4(af[i], aB + (uint32_t)(16 * i) * ROW_B + ko);
            #pragma unroll
            for (int jj = 0; jj < 4; jj++)
                ldsm4(bf[jj], bB + (uint32_t)(16 * jj) * ROW_B + ko);

            #pragma unroll
            for (int i = 0; i < 4; i++)
                #pragma unroll
                for (int j = 0; j < 8; j++) {
                    const int jj = j >> 1, odd = j & 1;
                    mma16816(acc[i][j], af[i],
                             bf[jj][odd], bf[jj][2 + odd]);
                }
        }
    }

    float2 bj[8];
    #pragma unroll
    for (int j = 0; j < 8; j++)
        bj[j] = *(const float2*)(bias + col0 + wn + 8 * j + 2 * tg);

    #pragma unroll
    for (int i = 0; i < 4; i++) {
        const int r0 = row0 + wm + 16 * i + g;
        const int r1 = r0 + 8;
        #pragma unroll
        for (int j = 0; j < 8; j++) {
            const int c = col0 + wn + 8 * j + 2 * tg;
            const size_t i0 = (size_t)r0 * E_DIM + c;
            const size_t i1 = (size_t)r1 * E_DIM + c;
            float2 rv0 = *(const float2*)(res + i0);
            float2 rv1 = *(const float2*)(res + i1);
            float2 o0, o1;
            o0.x = acc[i][j][0] + bj[j].x + rv0.x;
            o0.y = acc[i][j][1] + bj[j].y + rv0.y;
            o1.x = acc[i][j][2] + bj[j].x + rv1.x;
            o1.y = acc[i][j][3] + bj[j].y + rv1.y;
            *(float2*)(C + i0) = o0;
            *(float2*)(C + i1) = o1;
        }
    }
}

// ---------------------------------------------------------------------------
// cos(x + rx) precompute -> fp16
// ---------------------------------------------------------------------------
__global__ void __launch_bounds__(256)
cosx_kernel(const float* __restrict__ x, const float* __restrict__ rx,
            __half* __restrict__ cx)
{
    const int i = blockIdx.x * 256 + threadIdx.x;
    float4 v0 = ((const float4*)x)[2 * i];
    float4 v1 = ((const float4*)x)[2 * i + 1];
    const int e = (i * 8) & 63;
    __half2 h[4];
    h[0] = __floats2half2_rn(cosf(v0.x + rx[e + 0]), cosf(v0.y + rx[e + 1]));
    h[1] = __floats2half2_rn(cosf(v0.z + rx[e + 2]), cosf(v0.w + rx[e + 3]));
    h[2] = __floats2half2_rn(cosf(v1.x + rx[e + 4]), cosf(v1.y + rx[e + 5]));
    h[3] = __floats2half2_rn(cosf(v1.z + rx[e + 6]), cosf(v1.w + rx[e + 7]));
    ((uint4*)cx)[i] = *(const uint4*)h;
}

// ---------------------------------------------------------------------------
// Transpose: in R x C (fp32) -> out C x R (fp16)
// ---------------------------------------------------------------------------
__global__ void __launch_bounds__(256)
transpose_kernel(const float* __restrict__ in, __half* __restrict__ out, int R, int C)
{
    __shared__ float t[32][33];
    const int c0 = blockIdx.x * 32, r0 = blockIdx.y * 32;
    #pragma unroll
    for (int j = 0; j < 4; j++)
        t[threadIdx.y + j * 8][threadIdx.x] =
            in[(size_t)(r0 + threadIdx.y + j * 8) * C + (c0 + threadIdx.x)];
    __syncthreads();
    #pragma unroll
    for (int j = 0; j < 4; j++)
        out[(size_t)(c0 + threadIdx.y + j * 8) * R + (r0 + threadIdx.x)] =
            __float2half_rn(t[threadIdx.x][threadIdx.y + j * 8]);
}

// ---------------------------------------------------------------------------
// W1/b1 -> fp16 (tiny prep)
// ---------------------------------------------------------------------------
__global__ void __launch_bounds__(256)
w1prep_kernel(const float* __restrict__ W1, const float* __restrict__ b1,
              __half* __restrict__ W1h, __half* __restrict__ b1h)
{
    const int i = blockIdx.x * 256 + threadIdx.x;
    if (i < NQ * FFN_DIM) W1h[i] = __float2half_rn(W1[i]);
    if (i < FFN_DIM)      b1h[i] = __float2half_rn(b1[i]);
}

// ---------------------------------------------------------------------------
// Row LayerNorm over E=768 — one warp per row, barrier-free.
// WRITE_Q: lanes 0-1 write q as DUPLICATED half2 (for HFMA2 producer).
// ---------------------------------------------------------------------------
template <bool WRITE_Q>
__global__ void __launch_bounds__(256)
ln_kernel(const float* __restrict__ in, const float* __restrict__ g,
          const float* __restrict__ b, const float* __restrict__ ry,
          float* __restrict__ out, __half2* __restrict__ q16d)
{
    const int wid  = threadIdx.x >> 5;
    const int lane = threadIdx.x & 31;
    const int m    = blockIdx.x * 8 + wid;
    const float* row = in + (size_t)m * E_DIM;

    float4 v[6];
    float s = 0.f, ss = 0.f;
    #pragma unroll
    for (int i = 0; i < 6; i++) {
        v[i] = *(const float4*)(row + lane * 4 + i * 128);
        s  += v[i].x + v[i].y + v[i].z + v[i].w;
        ss += v[i].x * v[i].x + v[i].y * v[i].y
            + v[i].z * v[i].z + v[i].w * v[i].w;
    }
    #pragma unroll
    for (int o = 16; o > 0; o >>= 1) {
        s  += __shfl_xor_sync(0xffffffffu, s,  o);
        ss += __shfl_xor_sync(0xffffffffu, ss, o);
    }

    const float mu  = s * (1.f / E_DIM);
    const float var = ss * (1.f / E_DIM) - mu * mu;
    const float inv = rsqrtf(var + LN_EPS);

    float* orow = out + (size_t)m * E_DIM;
    #pragma unroll
    for (int i = 0; i < 6; i++) {
        const int c = lane * 4 + i * 128;
        const float4 gv = *(const float4*)(g + c);
        const float4 bv = *(const float4*)(b + c);
        float4 y;
        y.x = (v[i].x - mu) * inv * gv.x + bv.x;
        y.y = (v[i].y - mu) * inv * gv.y + bv.y;
        y.z = (v[i].z - mu) * inv * gv.z + bv.z;
        y.w = (v[i].w - mu) * inv * gv.w + bv.w;
        *(float4*)(orow + c) = y;
        if (WRITE_Q && i == 0 && lane < 2) {
            const int c0 = lane * 4;
            __half2 d0 = __half2half2(__float2half_rn(cosf(y.x) * cosf(ry[c0 + 0])));
            __half2 d1 = __half2half2(__float2half_rn(cosf(y.y) * cosf(ry[c0 + 1])));
            __half2 d2 = __half2half2(__float2half_rn(cosf(y.z) * cosf(ry[c0 + 2])));
            __half2 d3 = __half2half2(__float2half_rn(cosf(y.w) * cosf(ry[c0 + 3])));
            uint4 pk;
            pk.x = *(uint32_t*)&d0; pk.y = *(uint32_t*)&d1;
            pk.z = *(uint32_t*)&d2; pk.w = *(uint32_t*)&d3;
            *(uint4*)(q16d + (size_t)m * NQ + c0) = pk;
        }
    }
}

// ---------------------------------------------------------------------------
// Launch
// ---------------------------------------------------------------------------
extern "C" void kernel_launch(void* const* d_in, const int* in_sizes, int n_in,
                              void* d_out, int out_size)
{
    const float* x   = (const float*)d_in[0];
    const float* rx  = (const float*)d_in[1];
    const float* ry  = (const float*)d_in[2];
    const float* Wc  = (const float*)d_in[3];
    const float* bc  = (const float*)d_in[4];
    const float* W1  = (const float*)d_in[5];
    const float* b1  = (const float*)d_in[6];
    const float* W2  = (const float*)d_in[7];
    const float* b2  = (const float*)d_in[8];
    const float* g1  = (const float*)d_in[9];
    const float* be1 = (const float*)d_in[10];
    const float* g2  = (const float*)d_in[11];
    const float* be2 = (const float*)d_in[12];
    float* out = (float*)d_out;

    __half *cx, *WcT, *W2T, *W1h, *b1h;
    __half2* q16d;
    float *z, *x1, *f;
    cudaGetSymbolAddress((void**)&cx,   g_cx);
    cudaGetSymbolAddress((void**)&z,    g_z);
    cudaGetSymbolAddress((void**)&x1,   g_x1);
    cudaGetSymbolAddress((void**)&q16d, g_q16d);
    cudaGetSymbolAddress((void**)&f,    g_f);
    cudaGetSymbolAddress((void**)&WcT,  g_WcT);
    cudaGetSymbolAddress((void**)&W2T,  g_W2T);
    cudaGetSymbolAddress((void**)&W1h,  g_W1h);
    cudaGetSymbolAddress((void**)&b1h,  g_b1h);

    cudaFuncSetAttribute(gemm_mma_kernel,
                         cudaFuncAttributeMaxDynamicSharedMemorySize, SMEM1_BYTES);
    cudaFuncSetAttribute(gemm_ffn_kernel,
                         cudaFuncAttributeMaxDynamicSharedMemorySize, SMEM2_BYTES);

    // 0) weight prep (fp16) + cos precompute (fp16)
    transpose_kernel<<<dim3(E_DIM / 32, E_DIM / 32), dim3(32, 8)>>>(Wc, WcT, E_DIM, E_DIM);
    transpose_kernel<<<dim3(E_DIM / 32, FFN_DIM / 32), dim3(32, 8)>>>(W2, W2T, FFN_DIM, E_DIM);
    w1prep_kernel<<<(NQ * FFN_DIM + 255) / 256, 256>>>(W1, b1, W1h, b1h);
    cosx_kernel<<<(M_ROWS * E_DIM / 8) / 256, 256>>>(x, rx, cx);

    // 1) z = cos(x+rx) @ Wc + bc + x        (fp16 mma)
    gemm_mma_kernel<<<dim3(E_DIM / 128, M_ROWS / 256), 256, SMEM1_BYTES>>>(
        cx, WcT, bc, x, z, E_DIM, E_DIM / KT);

    // 2) x1 = LN(z); q16d = dup(cos(x1[:, :8]) * cos(ry))
    ln_kernel<true><<<M_ROWS / 8, 256>>>(z, g1, be1, ry, x1, q16d);

    // 3+4) f = relu(q@W1+b1) @ W2 + b2 + x1   (fused producer + fp16 mma)
    gemm_ffn_kernel<<<dim3(E_DIM / 128, M_ROWS / 256), 256, SMEM2_BYTES>>>(
        q16d, W1h, b1h, W2T, b2, x1, f, FFN_DIM, FFN_DIM / KT);

    // 5) out = LN(f)
    ln_kernel<false><<<M_ROWS / 8, 256>>>(f, g2, be2, nullptr, out, nullptr);
}

// round 15
// speedup vs baseline: 1.9653x; 1.2448x over previous
#include <cuda_runtime.h>
#include <cuda_fp16.h>
#include <math.h>
#include <stdint.h>

// Problem constants
#define M_ROWS   16384      // B*S
#define E_DIM    768
#define NQ       8
#define FFN_DIM  3072
#define LN_EPS   1e-5f

// ---------------------------------------------------------------------------
// Scratch (device globals: no cudaMalloc allowed)
// ---------------------------------------------------------------------------
__device__ __half g_cx [M_ROWS * E_DIM];    // cos(x + rx), fp16
__device__ float  g_z  [M_ROWS * E_DIM];    // pre-LN1
__device__ float  g_x1 [M_ROWS * E_DIM];    // LN1 output
__device__ float  g_q  [M_ROWS * NQ];
__device__ __half g_h  [M_ROWS * FFN_DIM];  // relu(q@W1+b1), fp16
__device__ float  g_f  [M_ROWS * E_DIM];    // pre-LN2
__device__ __half g_WcT[E_DIM * E_DIM];     // Wc^T, fp16
__device__ __half g_W2T[E_DIM * FFN_DIM];   // W2^T, fp16

// ---------------------------------------------------------------------------
// Helpers (baseline PTX only — compute_103 has no 'a' features)
// ---------------------------------------------------------------------------
__device__ __forceinline__ uint32_t smem_u32(const void* p) {
    uint32_t a;
    asm("{ .reg .u64 t; cvta.to.shared.u64 t, %1; cvt.u32.u64 %0, t; }"
        : "=r"(a) : "l"(p));
    return a;
}

__device__ __forceinline__ void cp16(uint32_t s, const void* g) {
    asm volatile("cp.async.ca.shared.global [%0], [%1], 16;" :: "r"(s), "l"(g));
}
#define CP_COMMIT() asm volatile("cp.async.commit_group;" ::: "memory")
#define CP_WAIT(n)  asm volatile("cp.async.wait_group %0;" :: "n"(n) : "memory")

__device__ __forceinline__ void ldsm4(uint32_t* r, uint32_t addr) {
    asm volatile("ldmatrix.sync.aligned.m8n8.x4.shared.b16 {%0,%1,%2,%3}, [%4];"
        : "=r"(r[0]), "=r"(r[1]), "=r"(r[2]), "=r"(r[3]) : "r"(addr));
}

__device__ __forceinline__ void mma16816(float* c, const uint32_t* a,
                                         uint32_t b0, uint32_t b1) {
    asm volatile(
        "mma.sync.aligned.m16n8k16.row.col.f32.f16.f16.f32 "
        "{%0,%1,%2,%3}, {%4,%5,%6,%7}, {%8,%9}, {%0,%1,%2,%3};"
        : "+f"(c[0]), "+f"(c[1]), "+f"(c[2]), "+f"(c[3])
        : "r"(a[0]), "r"(a[1]), "r"(a[2]), "r"(a[3]), "r"(b0), "r"(b1));
}

// ---------------------------------------------------------------------------
// fp16 tensor-core GEMM (fp32 accumulate) — round-10 proven config:
//   C[M, 768] = A[M, K] @ Bt[768, K]^T + bias + res
// CTA: 256 threads (8 warps, 4x2), tile 256(M) x 128(N), warp tile 64x64.
// KT=64, 3-stage cp.async pipeline, ONE __syncthreads per K-tile,
// fragment double-buffering across the 4 k16 steps.
// ---------------------------------------------------------------------------
#define KT        64
#define ROW_B     144                       // smem row stride bytes
#define A_BYTES   (256 * ROW_B)             // 36864
#define B_BYTES   (128 * ROW_B)             // 18432
#define STAGE_BYTES (A_BYTES + B_BYTES)     // 55296
#define NSTAGE    3
#define SMEM_BYTES  (NSTAGE * STAGE_BYTES)  // 165888

__global__ void __launch_bounds__(256, 1)
gemm_mma_kernel(const __half* __restrict__ A, const __half* __restrict__ Bt,
                const float* __restrict__ bias, const float* __restrict__ res,
                float* __restrict__ C, int K, int NK)
{
    extern __shared__ char smem[];
    const uint32_t sbase = smem_u32(smem);

    const int tid  = threadIdx.x;
    const int w    = tid >> 5, lane = tid & 31;
    const int g    = lane >> 2, tg = lane & 3;
    const int row0 = blockIdx.y * 256;
    const int col0 = blockIdx.x * 128;
    const int wm   = (w >> 1) * 64;         // 0,64,128,192
    const int wn   = (w & 1) * 64;          // 0,64

    const int lrow = lane & 15;
    const int lsel = lane >> 4;

    const int crow = tid >> 3;              // 0..31
    const int cchk = tid & 7;               // 0..7
    const __half* Ag = A  + (size_t)(row0 + crow) * K + cchk * 8;
    const __half* Bg = Bt + (size_t)(col0 + crow) * K + cchk * 8;

    float acc[4][8][4];
    #pragma unroll
    for (int i = 0; i < 4; i++)
        #pragma unroll
        for (int j = 0; j < 8; j++)
            #pragma unroll
            for (int v = 0; v < 4; v++) acc[i][j][v] = 0.f;

    const uint32_t so = (uint32_t)crow * ROW_B + (uint32_t)cchk * 16u;

    auto issue = [&](int kt) {
        const int s = kt % NSTAGE;
        const int k0 = kt * KT;
        const uint32_t sA = sbase + (uint32_t)s * STAGE_BYTES;
        const uint32_t sB = sA + A_BYTES;
        #pragma unroll
        for (int p = 0; p < 8; p++)
            cp16(sA + so + (uint32_t)(32 * p) * ROW_B,
                 Ag + (size_t)(32 * p) * K + k0);
        #pragma unroll
        for (int p = 0; p < 4; p++)
            cp16(sB + so + (uint32_t)(32 * p) * ROW_B,
                 Bg + (size_t)(32 * p) * K + k0);
        CP_COMMIT();
    };

    issue(0); issue(1);

    uint32_t af[2][4][4];
    uint32_t bf[2][4][4];

    for (int kt = 0; kt < NK; kt++) {
        const int s = kt % NSTAGE;
        CP_WAIT(1);
        __syncthreads();
        if (kt + 2 < NK) issue(kt + 2); else CP_COMMIT();

        const uint32_t sA = sbase + (uint32_t)s * STAGE_BYTES;
        const uint32_t sB = sA + A_BYTES;
        const uint32_t aB = sA + (uint32_t)(wm + lrow) * ROW_B + (uint32_t)lsel * 16u;
        const uint32_t bB = sB + (uint32_t)(wn + lrow) * ROW_B + (uint32_t)lsel * 16u;

        #pragma unroll
        for (int i = 0; i < 4; i++)
            ldsm4(af[0][i], aB + (uint32_t)(16 * i) * ROW_B);
        #pragma unroll
        for (int jj = 0; jj < 4; jj++)
            ldsm4(bf[0][jj], bB + (uint32_t)(16 * jj) * ROW_B);

        #pragma unroll
        for (int t2 = 0; t2 < 4; t2++) {
            const int cur = t2 & 1, nxt = cur ^ 1;
            if (t2 < 3) {
                const uint32_t ko = (uint32_t)(t2 + 1) * 32u;
                #pragma unroll
                for (int i = 0; i < 4; i++)
                    ldsm4(af[nxt][i], aB + (uint32_t)(16 * i) * ROW_B + ko);
                #pragma unroll
                for (int jj = 0; jj < 4; jj++)
                    ldsm4(bf[nxt][jj], bB + (uint32_t)(16 * jj) * ROW_B + ko);
            }
            #pragma unroll
            for (int i = 0; i < 4; i++)
                #pragma unroll
                for (int j = 0; j < 8; j++) {
                    const int jj = j >> 1, odd = j & 1;
                    mma16816(acc[i][j], af[cur][i],
                             bf[cur][jj][odd], bf[cur][jj][2 + odd]);
                }
        }
    }

    // Epilogue: + bias + res -> C
    float2 bj[8];
    #pragma unroll
    for (int j = 0; j < 8; j++)
        bj[j] = *(const float2*)(bias + col0 + wn + 8 * j + 2 * tg);

    #pragma unroll
    for (int i = 0; i < 4; i++) {
        const int r0 = row0 + wm + 16 * i + g;
        const int r1 = r0 + 8;
        #pragma unroll
        for (int j = 0; j < 8; j++) {
            const int c = col0 + wn + 8 * j + 2 * tg;
            const size_t i0 = (size_t)r0 * E_DIM + c;
            const size_t i1 = (size_t)r1 * E_DIM + c;
            float2 rv0 = *(const float2*)(res + i0);
            float2 rv1 = *(const float2*)(res + i1);
            float2 o0, o1;
            o0.x = acc[i][j][0] + bj[j].x + rv0.x;
            o0.y = acc[i][j][1] + bj[j].y + rv0.y;
            o1.x = acc[i][j][2] + bj[j].x + rv1.x;
            o1.y = acc[i][j][3] + bj[j].y + rv1.y;
            *(float2*)(C + i0) = o0;
            *(float2*)(C + i1) = o1;
        }
    }
}

// ---------------------------------------------------------------------------
// cos(x + rx) precompute -> fp16. __cosf (SFU): abs err ~1e-5 over |arg|<~10,
// far below the fp16 rounding (5e-4) applied immediately after.
// ---------------------------------------------------------------------------
__global__ void __launch_bounds__(256)
cosx_kernel(const float* __restrict__ x, const float* __restrict__ rx,
            __half* __restrict__ cx)
{
    const int i = blockIdx.x * 256 + threadIdx.x;
    float4 v0 = ((const float4*)x)[2 * i];
    float4 v1 = ((const float4*)x)[2 * i + 1];
    const int e = (i * 8) & 63;
    __half2 h[4];
    h[0] = __floats2half2_rn(__cosf(v0.x + rx[e + 0]), __cosf(v0.y + rx[e + 1]));
    h[1] = __floats2half2_rn(__cosf(v0.z + rx[e + 2]), __cosf(v0.w + rx[e + 3]));
    h[2] = __floats2half2_rn(__cosf(v1.x + rx[e + 4]), __cosf(v1.y + rx[e + 5]));
    h[3] = __floats2half2_rn(__cosf(v1.z + rx[e + 6]), __cosf(v1.w + rx[e + 7]));
    ((uint4*)cx)[i] = *(const uint4*)h;
}

// ---------------------------------------------------------------------------
// Transpose: in R x C (fp32) -> out C x R (fp16)
// ---------------------------------------------------------------------------
__global__ void __launch_bounds__(256)
transpose_kernel(const float* __restrict__ in, __half* __restrict__ out, int R, int C)
{
    __shared__ float t[32][33];
    const int c0 = blockIdx.x * 32, r0 = blockIdx.y * 32;
    #pragma unroll
    for (int j = 0; j < 4; j++)
        t[threadIdx.y + j * 8][threadIdx.x] =
            in[(size_t)(r0 + threadIdx.y + j * 8) * C + (c0 + threadIdx.x)];
    __syncthreads();
    #pragma unroll
    for (int j = 0; j < 4; j++)
        out[(size_t)(c0 + threadIdx.y + j * 8) * R + (r0 + threadIdx.x)] =
            __float2half_rn(t[threadIdx.x][threadIdx.y + j * 8]);
}

// ---------------------------------------------------------------------------
// Row LayerNorm over E=768 — one warp per row, barrier-free.
// ---------------------------------------------------------------------------
template <bool WRITE_Q>
__global__ void __launch_bounds__(256)
ln_kernel(const float* __restrict__ in, const float* __restrict__ g,
          const float* __restrict__ b, const float* __restrict__ ry,
          float* __restrict__ out, float* __restrict__ q)
{
    const int wid  = threadIdx.x >> 5;
    const int lane = threadIdx.x & 31;
    const int m    = blockIdx.x * 8 + wid;
    const float* row = in + (size_t)m * E_DIM;

    float4 v[6];
    float s = 0.f, ss = 0.f;
    #pragma unroll
    for (int i = 0; i < 6; i++) {
        v[i] = *(const float4*)(row + lane * 4 + i * 128);
        s  += v[i].x + v[i].y + v[i].z + v[i].w;
        ss += v[i].x * v[i].x + v[i].y * v[i].y
            + v[i].z * v[i].z + v[i].w * v[i].w;
    }
    #pragma unroll
    for (int o = 16; o > 0; o >>= 1) {
        s  += __shfl_xor_sync(0xffffffffu, s,  o);
        ss += __shfl_xor_sync(0xffffffffu, ss, o);
    }

    const float mu  = s * (1.f / E_DIM);
    const float var = ss * (1.f / E_DIM) - mu * mu;
    const float inv = rsqrtf(var + LN_EPS);

    float* orow = out + (size_t)m * E_DIM;
    #pragma unroll
    for (int i = 0; i < 6; i++) {
        const int c = lane * 4 + i * 128;
        const float4 gv = *(const float4*)(g + c);
        const float4 bv = *(const float4*)(b + c);
        float4 y;
        y.x = (v[i].x - mu) * inv * gv.x + bv.x;
        y.y = (v[i].y - mu) * inv * gv.y + bv.y;
        y.z = (v[i].z - mu) * inv * gv.z + bv.z;
        y.w = (v[i].w - mu) * inv * gv.w + bv.w;
        *(float4*)(orow + c) = y;
        if (WRITE_Q && i == 0 && lane < 2) {
            const int c0 = lane * 4;
            q[(size_t)m * NQ + c0 + 0] = cosf(y.x) * cosf(ry[c0 + 0]);
            q[(size_t)m * NQ + c0 + 1] = cosf(y.y) * cosf(ry[c0 + 1]);
            q[(size_t)m * NQ + c0 + 2] = cosf(y.z) * cosf(ry[c0 + 2]);
            q[(size_t)m * NQ + c0 + 3] = cosf(y.w) * cosf(ry[c0 + 3]);
        }
    }
}

// ---------------------------------------------------------------------------
// FFN first layer (tiled): h = relu(q @ W1 + b1) -> fp16.
// ---------------------------------------------------------------------------
__global__ void __launch_bounds__(256)
ffn1_kernel(const float* __restrict__ q, const float* __restrict__ W1,
            const float* __restrict__ b1, __half* __restrict__ h)
{
    __shared__ float w1s[NQ][1024];
    __shared__ float b1s[1024];
    __shared__ float qs[256][NQ];

    const int col0 = blockIdx.x * 1024;
    const int m0   = blockIdx.y * 256;
    const int tid  = threadIdx.x;

    #pragma unroll
    for (int i = 0; i < NQ; i++)
        *(float4*)&w1s[i][tid * 4] =
            *(const float4*)(W1 + (size_t)i * FFN_DIM + col0 + tid * 4);
    *(float4*)&b1s[tid * 4] = *(const float4*)(b1 + col0 + tid * 4);
    {
        const int r = tid;
        float2 q01 = *(const float2*)(q + (size_t)(m0 + r) * NQ + 0);
        float2 q23 = *(const float2*)(q + (size_t)(m0 + r) * NQ + 2);
        float2 q45 = *(const float2*)(q + (size_t)(m0 + r) * NQ + 4);
        float2 q67 = *(const float2*)(q + (size_t)(m0 + r) * NQ + 6);
        qs[r][0] = q01.x; qs[r][1] = q01.y;
        qs[r][2] = q23.x; qs[r][3] = q23.y;
        qs[r][4] = q45.x; qs[r][5] = q45.y;
        qs[r][6] = q67.x; qs[r][7] = q67.y;
    }
    __syncthreads();

    float4 wr[NQ];
    #pragma unroll
    for (int i = 0; i < NQ; i++) wr[i] = *(float4*)&w1s[i][tid * 4];
    const float4 bb = *(float4*)&b1s[tid * 4];

    __half* hp = h + (size_t)m0 * FFN_DIM + col0 + tid * 4;
    for (int r = 0; r < 256; r++) {
        float4 acc = bb;
        #pragma unroll
        for (int i = 0; i < NQ; i++) {
            const float qv = qs[r][i];
            acc.x = fmaf(qv, wr[i].x, acc.x);
            acc.y = fmaf(qv, wr[i].y, acc.y);
            acc.z = fmaf(qv, wr[i].z, acc.z);
            acc.w = fmaf(qv, wr[i].w, acc.w);
        }
        __half2 p0 = __floats2half2_rn(fmaxf(acc.x, 0.f), fmaxf(acc.y, 0.f));
        __half2 p1 = __floats2half2_rn(fmaxf(acc.z, 0.f), fmaxf(acc.w, 0.f));
        uint2 pk = make_uint2(*(uint32_t*)&p0, *(uint32_t*)&p1);
        *(uint2*)(hp + (size_t)r * FFN_DIM) = pk;
    }
}

// ---------------------------------------------------------------------------
// Launch
// ---------------------------------------------------------------------------
extern "C" void kernel_launch(void* const* d_in, const int* in_sizes, int n_in,
                              void* d_out, int out_size)
{
    const float* x   = (const float*)d_in[0];
    const float* rx  = (const float*)d_in[1];
    const float* ry  = (const float*)d_in[2];
    const float* Wc  = (const float*)d_in[3];
    const float* bc  = (const float*)d_in[4];
    const float* W1  = (const float*)d_in[5];
    const float* b1  = (const float*)d_in[6];
    const float* W2  = (const float*)d_in[7];
    const float* b2  = (const float*)d_in[8];
    const float* g1  = (const float*)d_in[9];
    const float* be1 = (const float*)d_in[10];
    const float* g2  = (const float*)d_in[11];
    const float* be2 = (const float*)d_in[12];
    float* out = (float*)d_out;

    __half *cx, *h, *WcT, *W2T;
    float *z, *x1, *q, *f;
    cudaGetSymbolAddress((void**)&cx,  g_cx);
    cudaGetSymbolAddress((void**)&z,   g_z);
    cudaGetSymbolAddress((void**)&x1,  g_x1);
    cudaGetSymbolAddress((void**)&q,   g_q);
    cudaGetSymbolAddress((void**)&h,   g_h);
    cudaGetSymbolAddress((void**)&f,   g_f);
    cudaGetSymbolAddress((void**)&WcT, g_WcT);
    cudaGetSymbolAddress((void**)&W2T, g_W2T);

    cudaFuncSetAttribute(gemm_mma_kernel,
                         cudaFuncAttributeMaxDynamicSharedMemorySize, SMEM_BYTES);

    // 0) weight transposes (fp16) + cos precompute (fp16, SFU cos)
    transpose_kernel<<<dim3(E_DIM / 32, E_DIM / 32), dim3(32, 8)>>>(Wc, WcT, E_DIM, E_DIM);
    transpose_kernel<<<dim3(E_DIM / 32, FFN_DIM / 32), dim3(32, 8)>>>(W2, W2T, FFN_DIM, E_DIM);
    cosx_kernel<<<(M_ROWS * E_DIM / 8) / 256, 256>>>(x, rx, cx);

    // 1) z = cos(x+rx) @ Wc + bc + x        (fp16 mma + ldmatrix)
    gemm_mma_kernel<<<dim3(E_DIM / 128, M_ROWS / 256), 256, SMEM_BYTES>>>(
        cx, WcT, bc, x, z, E_DIM, E_DIM / KT);

    // 2) x1 = LN(z); q = cos(x1[:, :8]) * cos(ry)   (warp-per-row)
    ln_kernel<true><<<M_ROWS / 8, 256>>>(z, g1, be1, ry, x1, q);

    // 3) h = relu(q @ W1 + b1)  -> fp16
    ffn1_kernel<<<dim3(FFN_DIM / 1024, M_ROWS / 256), 256>>>(q, W1, b1, h);

    // 4) f = h @ W2 + b2 + x1               (fp16 mma + ldmatrix)
    gemm_mma_kernel<<<dim3(E_DIM / 128, M_ROWS / 256), 256, SMEM_BYTES>>>(
        h, W2T, b2, x1, f, FFN_DIM, FFN_DIM / KT);

    // 5) out = LN(f)                        (warp-per-row)
    ln_kernel<false><<<M_ROWS / 8, 256>>>(f, g2, be2, nullptr, out, nullptr);
}

// round 16
// speedup vs baseline: 1.9680x; 1.0014x over previous
#include <cuda_runtime.h>
#include <cuda_fp16.h>
#include <math.h>
#include <stdint.h>

// Problem constants
#define M_ROWS   16384      // B*S
#define E_DIM    768
#define NQ       8
#define FFN_DIM  3072
#define LN_EPS   1e-5f

// ---------------------------------------------------------------------------
// Scratch (device globals: no cudaMalloc allowed)
// ---------------------------------------------------------------------------
__device__ __half g_cx [M_ROWS * E_DIM];    // cos(x + rx), fp16
__device__ __half g_z  [M_ROWS * E_DIM];    // pre-LN1, fp16
__device__ __half g_x1 [M_ROWS * E_DIM];    // LN1 output, fp16
__device__ float  g_q  [M_ROWS * NQ];
__device__ __half g_h  [M_ROWS * FFN_DIM];  // relu(q@W1+b1), fp16
__device__ __half g_f  [M_ROWS * E_DIM];    // pre-LN2, fp16
__device__ __half g_WcT[E_DIM * E_DIM];     // Wc^T, fp16
__device__ __half g_W2T[E_DIM * FFN_DIM];   // W2^T, fp16

// ---------------------------------------------------------------------------
// Helpers (baseline PTX only — compute_103 has no 'a' features)
// ---------------------------------------------------------------------------
__device__ __forceinline__ uint32_t smem_u32(const void* p) {
    uint32_t a;
    asm("{ .reg .u64 t; cvta.to.shared.u64 t, %1; cvt.u32.u64 %0, t; }"
        : "=r"(a) : "l"(p));
    return a;
}

__device__ __forceinline__ void cp16(uint32_t s, const void* g) {
    asm volatile("cp.async.ca.shared.global [%0], [%1], 16;" :: "r"(s), "l"(g));
}
#define CP_COMMIT() asm volatile("cp.async.commit_group;" ::: "memory")
#define CP_WAIT(n)  asm volatile("cp.async.wait_group %0;" :: "n"(n) : "memory")

__device__ __forceinline__ void ldsm4(uint32_t* r, uint32_t addr) {
    asm volatile("ldmatrix.sync.aligned.m8n8.x4.shared.b16 {%0,%1,%2,%3}, [%4];"
        : "=r"(r[0]), "=r"(r[1]), "=r"(r[2]), "=r"(r[3]) : "r"(addr));
}

__device__ __forceinline__ void mma16816(float* c, const uint32_t* a,
                                         uint32_t b0, uint32_t b1) {
    asm volatile(
        "mma.sync.aligned.m16n8k16.row.col.f32.f16.f16.f32 "
        "{%0,%1,%2,%3}, {%4,%5,%6,%7}, {%8,%9}, {%0,%1,%2,%3};"
        : "+f"(c[0]), "+f"(c[1]), "+f"(c[2]), "+f"(c[3])
        : "r"(a[0]), "r"(a[1]), "r"(a[2]), "r"(a[3]), "r"(b0), "r"(b1));
}

// residual loaders (fp32 or fp16 -> float2)
__device__ __forceinline__ float2 ldres(const float* p)  { return *(const float2*)p; }
__device__ __forceinline__ float2 ldres(const __half* p) { return __half22float2(*(const __half2*)p); }

// ---------------------------------------------------------------------------
// fp16 tensor-core GEMM (fp32 accumulate) — round-10 proven config:
//   C[M, 768] (fp16) = A[M, K] @ Bt[768, K]^T + bias + res
// CTA: 256 threads (8 warps, 4x2), tile 256(M) x 128(N), warp tile 64x64.
// KT=64, 3-stage cp.async pipeline, ONE __syncthreads per K-tile,
// fragment double-buffering across the 4 k16 steps.
// ---------------------------------------------------------------------------
#define KT        64
#define ROW_B     144                       // smem row stride bytes
#define A_BYTES   (256 * ROW_B)             // 36864
#define B_BYTES   (128 * ROW_B)             // 18432
#define STAGE_BYTES (A_BYTES + B_BYTES)     // 55296
#define NSTAGE    3
#define SMEM_BYTES  (NSTAGE * STAGE_BYTES)  // 165888

template <typename ResT>
__global__ void __launch_bounds__(256, 1)
gemm_mma_kernel(const __half* __restrict__ A, const __half* __restrict__ Bt,
                const float* __restrict__ bias, const ResT* __restrict__ res,
                __half* __restrict__ C, int K, int NK)
{
    extern __shared__ char smem[];
    const uint32_t sbase = smem_u32(smem);

    const int tid  = threadIdx.x;
    const int w    = tid >> 5, lane = tid & 31;
    const int g    = lane >> 2, tg = lane & 3;
    const int row0 = blockIdx.y * 256;
    const int col0 = blockIdx.x * 128;
    const int wm   = (w >> 1) * 64;         // 0,64,128,192
    const int wn   = (w & 1) * 64;          // 0,64

    const int lrow = lane & 15;
    const int lsel = lane >> 4;

    const int crow = tid >> 3;              // 0..31
    const int cchk = tid & 7;               // 0..7
    const __half* Ag = A  + (size_t)(row0 + crow) * K + cchk * 8;
    const __half* Bg = Bt + (size_t)(col0 + crow) * K + cchk * 8;

    float acc[4][8][4];
    #pragma unroll
    for (int i = 0; i < 4; i++)
        #pragma unroll
        for (int j = 0; j < 8; j++)
            #pragma unroll
            for (int v = 0; v < 4; v++) acc[i][j][v] = 0.f;

    const uint32_t so = (uint32_t)crow * ROW_B + (uint32_t)cchk * 16u;

    auto issue = [&](int kt) {
        const int s = kt % NSTAGE;
        const int k0 = kt * KT;
        const uint32_t sA = sbase + (uint32_t)s * STAGE_BYTES;
        const uint32_t sB = sA + A_BYTES;
        #pragma unroll
        for (int p = 0; p < 8; p++)
            cp16(sA + so + (uint32_t)(32 * p) * ROW_B,
                 Ag + (size_t)(32 * p) * K + k0);
        #pragma unroll
        for (int p = 0; p < 4; p++)
            cp16(sB + so + (uint32_t)(32 * p) * ROW_B,
                 Bg + (size_t)(32 * p) * K + k0);
        CP_COMMIT();
    };

    issue(0); issue(1);

    uint32_t af[2][4][4];
    uint32_t bf[2][4][4];

    for (int kt = 0; kt < NK; kt++) {
        const int s = kt % NSTAGE;
        CP_WAIT(1);
        __syncthreads();
        if (kt + 2 < NK) issue(kt + 2); else CP_COMMIT();

        const uint32_t sA = sbase + (uint32_t)s * STAGE_BYTES;
        const uint32_t sB = sA + A_BYTES;
        const uint32_t aB = sA + (uint32_t)(wm + lrow) * ROW_B + (uint32_t)lsel * 16u;
        const uint32_t bB = sB + (uint32_t)(wn + lrow) * ROW_B + (uint32_t)lsel * 16u;

        #pragma unroll
        for (int i = 0; i < 4; i++)
            ldsm4(af[0][i], aB + (uint32_t)(16 * i) * ROW_B);
        #pragma unroll
        for (int jj = 0; jj < 4; jj++)
            ldsm4(bf[0][jj], bB + (uint32_t)(16 * jj) * ROW_B);

        #pragma unroll
        for (int t2 = 0; t2 < 4; t2++) {
            const int cur = t2 & 1, nxt = cur ^ 1;
            if (t2 < 3) {
                const uint32_t ko = (uint32_t)(t2 + 1) * 32u;
                #pragma unroll
                for (int i = 0; i < 4; i++)
                    ldsm4(af[nxt][i], aB + (uint32_t)(16 * i) * ROW_B + ko);
                #pragma unroll
                for (int jj = 0; jj < 4; jj++)
                    ldsm4(bf[nxt][jj], bB + (uint32_t)(16 * jj) * ROW_B + ko);
            }
            #pragma unroll
            for (int i = 0; i < 4; i++)
                #pragma unroll
                for (int j = 0; j < 8; j++) {
                    const int jj = j >> 1, odd = j & 1;
                    mma16816(acc[i][j], af[cur][i],
                             bf[cur][jj][odd], bf[cur][jj][2 + odd]);
                }
        }
    }

    // Epilogue: + bias + res -> C (fp16)
    float2 bj[8];
    #pragma unroll
    for (int j = 0; j < 8; j++)
        bj[j] = *(const float2*)(bias + col0 + wn + 8 * j + 2 * tg);

    #pragma unroll
    for (int i = 0; i < 4; i++) {
        const int r0 = row0 + wm + 16 * i + g;
        const int r1 = r0 + 8;
        #pragma unroll
        for (int j = 0; j < 8; j++) {
            const int c = col0 + wn + 8 * j + 2 * tg;
            const size_t i0 = (size_t)r0 * E_DIM + c;
            const size_t i1 = (size_t)r1 * E_DIM + c;
            float2 rv0 = ldres(res + i0);
            float2 rv1 = ldres(res + i1);
            __half2 o0 = __floats2half2_rn(acc[i][j][0] + bj[j].x + rv0.x,
                                           acc[i][j][1] + bj[j].y + rv0.y);
            __half2 o1 = __floats2half2_rn(acc[i][j][2] + bj[j].x + rv1.x,
                                           acc[i][j][3] + bj[j].y + rv1.y);
            *(uint32_t*)(C + i0) = *(uint32_t*)&o0;
            *(uint32_t*)(C + i1) = *(uint32_t*)&o1;
        }
    }
}

// ---------------------------------------------------------------------------
// cos(x + rx) precompute -> fp16 (SFU __cosf)
// ---------------------------------------------------------------------------
__global__ void __launch_bounds__(256)
cosx_kernel(const float* __restrict__ x, const float* __restrict__ rx,
            __half* __restrict__ cx)
{
    const int i = blockIdx.x * 256 + threadIdx.x;
    float4 v0 = ((const float4*)x)[2 * i];
    float4 v1 = ((const float4*)x)[2 * i + 1];
    const int e = (i * 8) & 63;
    __half2 h[4];
    h[0] = __floats2half2_rn(__cosf(v0.x + rx[e + 0]), __cosf(v0.y + rx[e + 1]));
    h[1] = __floats2half2_rn(__cosf(v0.z + rx[e + 2]), __cosf(v0.w + rx[e + 3]));
    h[2] = __floats2half2_rn(__cosf(v1.x + rx[e + 4]), __cosf(v1.y + rx[e + 5]));
    h[3] = __floats2half2_rn(__cosf(v1.z + rx[e + 6]), __cosf(v1.w + rx[e + 7]));
    ((uint4*)cx)[i] = *(const uint4*)h;
}

// ---------------------------------------------------------------------------
// Transpose: in R x C (fp32) -> out C x R (fp16)
// ---------------------------------------------------------------------------
__global__ void __launch_bounds__(256)
transpose_kernel(const float* __restrict__ in, __half* __restrict__ out, int R, int C)
{
    __shared__ float t[32][33];
    const int c0 = blockIdx.x * 32, r0 = blockIdx.y * 32;
    #pragma unroll
    for (int j = 0; j < 4; j++)
        t[threadIdx.y + j * 8][threadIdx.x] =
            in[(size_t)(r0 + threadIdx.y + j * 8) * C + (c0 + threadIdx.x)];
    __syncthreads();
    #pragma unroll
    for (int j = 0; j < 4; j++)
        out[(size_t)(c0 + threadIdx.y + j * 8) * R + (r0 + threadIdx.x)] =
            __float2half_rn(t[threadIdx.x][threadIdx.y + j * 8]);
}

// ---------------------------------------------------------------------------
// Row LayerNorm over E=768 (fp16 input) — one warp per row, barrier-free.
// Lane holds 3 x 8 halves (elems lane*8 + i*256). Stats in fp32.
// OutT: __half (x1) or float (final out). WRITE_Q: lane 0 owns elems 0..7.
// ---------------------------------------------------------------------------
template <bool WRITE_Q, typename OutT>
__global__ void __launch_bounds__(256)
ln_kernel(const __half* __restrict__ in, const float* __restrict__ g,
          const float* __restrict__ b, const float* __restrict__ ry,
          OutT* __restrict__ out, float* __restrict__ q)
{
    const int wid  = threadIdx.x >> 5;
    const int lane = threadIdx.x & 31;
    const int m    = blockIdx.x * 8 + wid;
    const __half* row = in + (size_t)m * E_DIM;

    float v[3][8];
    float s = 0.f, ss = 0.f;
    #pragma unroll
    for (int i = 0; i < 3; i++) {
        uint4 raw = *(const uint4*)(row + lane * 8 + i * 256);
        const __half2* hp = (const __half2*)&raw;
        #pragma unroll
        for (int k = 0; k < 4; k++) {
            float2 f2 = __half22float2(hp[k]);
            v[i][2 * k]     = f2.x;
            v[i][2 * k + 1] = f2.y;
            s  += f2.x + f2.y;
            ss += f2.x * f2.x + f2.y * f2.y;
        }
    }
    #pragma unroll
    for (int o = 16; o > 0; o >>= 1) {
        s  += __shfl_xor_sync(0xffffffffu, s,  o);
        ss += __shfl_xor_sync(0xffffffffu, ss, o);
    }

    const float mu  = s * (1.f / E_DIM);
    const float var = ss * (1.f / E_DIM) - mu * mu;
    const float inv = rsqrtf(var + LN_EPS);

    OutT* orow = out + (size_t)m * E_DIM;
    #pragma unroll
    for (int i = 0; i < 3; i++) {
        const int c = lane * 8 + i * 256;
        const float4 gv0 = *(const float4*)(g + c);
        const float4 gv1 = *(const float4*)(g + c + 4);
        const float4 bv0 = *(const float4*)(b + c);
        const float4 bv1 = *(const float4*)(b + c + 4);
        float y[8];
        y[0] = (v[i][0] - mu) * inv * gv0.x + bv0.x;
        y[1] = (v[i][1] - mu) * inv * gv0.y + bv0.y;
        y[2] = (v[i][2] - mu) * inv * gv0.z + bv0.z;
        y[3] = (v[i][3] - mu) * inv * gv0.w + bv0.w;
        y[4] = (v[i][4] - mu) * inv * gv1.x + bv1.x;
        y[5] = (v[i][5] - mu) * inv * gv1.y + bv1.y;
        y[6] = (v[i][6] - mu) * inv * gv1.z + bv1.z;
        y[7] = (v[i][7] - mu) * inv * gv1.w + bv1.w;

        if (sizeof(OutT) == 4) {
            float4 o0 = make_float4(y[0], y[1], y[2], y[3]);
            float4 o1 = make_float4(y[4], y[5], y[6], y[7]);
            *(float4*)((float*)orow + c)     = o0;
            *(float4*)((float*)orow + c + 4) = o1;
        } else {
            __half2 hh[4];
            hh[0] = __floats2half2_rn(y[0], y[1]);
            hh[1] = __floats2half2_rn(y[2], y[3]);
            hh[2] = __floats2half2_rn(y[4], y[5]);
            hh[3] = __floats2half2_rn(y[6], y[7]);
            *(uint4*)((__half*)orow + c) = *(const uint4*)hh;
        }
        if (WRITE_Q && i == 0 && lane == 0) {
            #pragma unroll
            for (int k = 0; k < 8; k++)
                q[(size_t)m * NQ + k] = cosf(y[k]) * cosf(ry[k]);
        }
    }
}

// ---------------------------------------------------------------------------
// FFN first layer (tiled): h = relu(q @ W1 + b1) -> fp16.
// ---------------------------------------------------------------------------
__global__ void __launch_bounds__(256)
ffn1_kernel(const float* __restrict__ q, const float* __restrict__ W1,
            const float* __restrict__ b1, __half* __restrict__ h)
{
    __shared__ float w1s[NQ][1024];
    __shared__ float b1s[1024];
    __shared__ float qs[256][NQ];

    const int col0 = blockIdx.x * 1024;
    const int m0   = blockIdx.y * 256;
    const int tid  = threadIdx.x;

    #pragma unroll
    for (int i = 0; i < NQ; i++)
        *(float4*)&w1s[i][tid * 4] =
            *(const float4*)(W1 + (size_t)i * FFN_DIM + col0 + tid * 4);
    *(float4*)&b1s[tid * 4] = *(const float4*)(b1 + col0 + tid * 4);
    {
        const int r = tid;
        float2 q01 = *(const float2*)(q + (size_t)(m0 + r) * NQ + 0);
        float2 q23 = *(const float2*)(q + (size_t)(m0 + r) * NQ + 2);
        float2 q45 = *(const float2*)(q + (size_t)(m0 + r) * NQ + 4);
        float2 q67 = *(const float2*)(q + (size_t)(m0 + r) * NQ + 6);
        qs[r][0] = q01.x; qs[r][1] = q01.y;
        qs[r][2] = q23.x; qs[r][3] = q23.y;
        qs[r][4] = q45.x; qs[r][5] = q45.y;
        qs[r][6] = q67.x; qs[r][7] = q67.y;
    }
    __syncthreads();

    float4 wr[NQ];
    #pragma unroll
    for (int i = 0; i < NQ; i++) wr[i] = *(float4*)&w1s[i][tid * 4];
    const float4 bb = *(float4*)&b1s[tid * 4];

    __half* hp = h + (size_t)m0 * FFN_DIM + col0 + tid * 4;
    for (int r = 0; r < 256; r++) {
        float4 acc = bb;
        #pragma unroll
        for (int i = 0; i < NQ; i++) {
            const float qv = qs[r][i];
            acc.x = fmaf(qv, wr[i].x, acc.x);
            acc.y = fmaf(qv, wr[i].y, acc.y);
            acc.z = fmaf(qv, wr[i].z, acc.z);
            acc.w = fmaf(qv, wr[i].w, acc.w);
        }
        __half2 p0 = __floats2half2_rn(fmaxf(acc.x, 0.f), fmaxf(acc.y, 0.f));
        __half2 p1 = __floats2half2_rn(fmaxf(acc.z, 0.f), fmaxf(acc.w, 0.f));
        uint2 pk = make_uint2(*(uint32_t*)&p0, *(uint32_t*)&p1);
        *(uint2*)(hp + (size_t)r * FFN_DIM) = pk;
    }
}

// ---------------------------------------------------------------------------
// Launch
// ---------------------------------------------------------------------------
extern "C" void kernel_launch(void* const* d_in, const int* in_sizes, int n_in,
                              void* d_out, int out_size)
{
    const float* x   = (const float*)d_in[0];
    const float* rx  = (const float*)d_in[1];
    const float* ry  = (const float*)d_in[2];
    const float* Wc  = (const float*)d_in[3];
    const float* bc  = (const float*)d_in[4];
    const float* W1  = (const float*)d_in[5];
    const float* b1  = (const float*)d_in[6];
    const float* W2  = (const float*)d_in[7];
    const float* b2  = (const float*)d_in[8];
    const float* g1  = (const float*)d_in[9];
    const float* be1 = (const float*)d_in[10];
    const float* g2  = (const float*)d_in[11];
    const float* be2 = (const float*)d_in[12];
    float* out = (float*)d_out;

    __half *cx, *z, *x1, *h, *f, *WcT, *W2T;
    float *q;
    cudaGetSymbolAddress((void**)&cx,  g_cx);
    cudaGetSymbolAddress((void**)&z,   g_z);
    cudaGetSymbolAddress((void**)&x1,  g_x1);
    cudaGetSymbolAddress((void**)&q,   g_q);
    cudaGetSymbolAddress((void**)&h,   g_h);
    cudaGetSymbolAddress((void**)&f,   g_f);
    cudaGetSymbolAddress((void**)&WcT, g_WcT);
    cudaGetSymbolAddress((void**)&W2T, g_W2T);

    cudaFuncSetAttribute(gemm_mma_kernel<float>,
                         cudaFuncAttributeMaxDynamicSharedMemorySize, SMEM_BYTES);
    cudaFuncSetAttribute(gemm_mma_kernel<__half>,
                         cudaFuncAttributeMaxDynamicSharedMemorySize, SMEM_BYTES);

    // 0) weight transposes (fp16) + cos precompute (fp16, SFU cos)
    transpose_kernel<<<dim3(E_DIM / 32, E_DIM / 32), dim3(32, 8)>>>(Wc, WcT, E_DIM, E_DIM);
    transpose_kernel<<<dim3(E_DIM / 32, FFN_DIM / 32), dim3(32, 8)>>>(W2, W2T, FFN_DIM, E_DIM);
    cosx_kernel<<<(M_ROWS * E_DIM / 8) / 256, 256>>>(x, rx, cx);

    // 1) z = cos(x+rx) @ Wc + bc + x        (fp16 mma; z fp16)
    gemm_mma_kernel<float><<<dim3(E_DIM / 128, M_ROWS / 256), 256, SMEM_BYTES>>>(
        cx, WcT, bc, x, z, E_DIM, E_DIM / KT);

    // 2) x1 = LN(z) (fp16); q = cos(x1[:, :8]) * cos(ry)
    ln_kernel<true, __half><<<M_ROWS / 8, 256>>>(z, g1, be1, ry, x1, q);

    // 3) h = relu(q @ W1 + b1)  -> fp16
    ffn1_kernel<<<dim3(FFN_DIM / 1024, M_ROWS / 256), 256>>>(q, W1, b1, h);

    // 4) f = h @ W2 + b2 + x1               (fp16 mma; f fp16, res fp16)
    gemm_mma_kernel<__half><<<dim3(E_DIM / 128, M_ROWS / 256), 256, SMEM_BYTES>>>(
        h, W2T, b2, x1, f, FFN_DIM, FFN_DIM / KT);

    // 5) out = LN(f) -> fp32 harness buffer
    ln_kernel<false, float><<<M_ROWS / 8, 256>>>(f, g2, be2, nullptr, out, nullptr);
}